// round 13
// baseline (speedup 1.0000x reference)
#include <cuda_runtime.h>
#include <cstdint>

#define FULL 0xffffffffu

static constexpr int S = 8;
static constexpr int N = 4096;
static constexpr int M = 64;
static constexpr int SN = S * N;

static constexpr int CPO   = 128;                 // cells per octave
static constexpr int CELLS = 17 * CPO;            // 2176
static constexpr int EBASE = (127 - 12) * CPO;    // s_min = 2^-12
static constexpr int CSHIFT = 16;                 // 23 - log2(CPO)
static constexpr int PACK_BLOCKS = SN / 4 / 256;  // 32
static constexpr int CPW = 31;                    // cells per warp
static constexpr int WARPS_PER_TT = (CELLS + CPW - 1) / CPW;   // 71
static constexpr int TAB_WARPS = 4 * WARPS_PER_TT;             // 284
static constexpr int TAB_BLOCKS = (TAB_WARPS + 7) / 8;         // 36

__device__ float4 g_pos4[SN];             // (x, y, z, type)
__device__ float2 g_tab[4 * CELLS * 32];  // (slope, intercept)[tt][cell][g]

// ---------------- packed f32x2 helpers (sm_103a FFMA2) ----------------
__device__ __forceinline__ void ffma2(unsigned long long& d,
                                      unsigned long long a,
                                      unsigned long long b) {
    asm("fma.rn.f32x2 %0, %1, %2, %0;" : "+l"(d) : "l"(a), "l"(b));
}
__device__ __forceinline__ unsigned long long mul2(unsigned long long a,
                                                   unsigned long long b) {
    unsigned long long d;
    asm("mul.rn.f32x2 %0, %1, %2;" : "=l"(d) : "l"(a), "l"(b));
    return d;
}
__device__ __forceinline__ unsigned long long pack2(float lo, float hi) {
    unsigned long long d;
    asm("mov.b64 %0, {%1, %2};" : "=l"(d) : "f"(lo), "f"(hi));
    return d;
}
__device__ __forceinline__ void unpack2(unsigned long long v,
                                        float& lo, float& hi) {
    asm("mov.b64 {%0, %1}, %2;" : "=f"(lo), "=f"(hi) : "l"(v));
}

// ---------------------------------------------------------------------------
// Prep kernel.
//  blocks [0, PACK_BLOCKS): pack positions+type into float4 (vectorized)
//  blocks [PACK_BLOCKS, +TAB_BLOCKS): PWL table build. ALL weights staged to
//  shared in ONE parallel load round; every lane recomputes td/v8 from
//  shared (pure ALU) -- no serial global-load chain anywhere.
// ---------------------------------------------------------------------------
__global__ void prep_kernel(
    const float* __restrict__ pos, const int* __restrict__ types,
    const float* __restrict__ es1_w, const float* __restrict__ es1_b,
    const float* __restrict__ es2_w, const float* __restrict__ es2_b,
    const float* __restrict__ fs1_w, const float* __restrict__ fs1_b,
    const float* __restrict__ fs2_w, const float* __restrict__ fs2_b,
    const float* __restrict__ en1_w, const float* __restrict__ en1_b,
    const float* __restrict__ en2_w, const float* __restrict__ en2_b,
    const float* __restrict__ en3_w, const float* __restrict__ en3_b)
{
    if (blockIdx.x < PACK_BLOCKS) {
        const int idx = blockIdx.x * blockDim.x + threadIdx.x;
        const float4* pv = reinterpret_cast<const float4*>(pos) + idx * 3;
        const float4 a = pv[0], b = pv[1], c = pv[2];
        const int4 t = reinterpret_cast<const int4*>(types)[idx];
        float4* o = g_pos4 + idx * 4;
        o[0] = make_float4(a.x, a.y, a.z, (float)t.x);
        o[1] = make_float4(a.w, b.x, b.y, (float)t.y);
        o[2] = make_float4(b.z, b.w, c.x, (float)t.z);
        o[3] = make_float4(c.y, c.z, c.w, (float)t.w);
        return;
    }

    __shared__ float s_es1w[8],  s_es1b[4],  s_es2w[16], s_es2b[4];
    __shared__ float s_fs1w[16], s_fs1b[4],  s_fs2w[16], s_fs2b[4];
    __shared__ float s_en1w[32], s_en1b[8],  s_en2w[128], s_en2b[16];
    __shared__ float s_en3w[512], s_en3b[32];
    __shared__ float s_h2[8][32][16];

    const int t = threadIdx.x;
    // ---- one parallel load round: disjoint thread ranges ----
    if      (t < 8)   s_es1w[t]       = es1_w[t];
    else if (t < 12)  s_es1b[t - 8]   = es1_b[t - 8];
    else if (t < 28)  s_es2w[t - 12]  = es2_w[t - 12];
    else if (t < 32)  s_es2b[t - 28]  = es2_b[t - 28];
    else if (t < 48)  s_fs1w[t - 32]  = fs1_w[t - 32];
    else if (t < 52)  s_fs1b[t - 48]  = fs1_b[t - 48];
    else if (t < 68)  s_fs2w[t - 52]  = fs2_w[t - 52];
    else if (t < 72)  s_fs2b[t - 68]  = fs2_b[t - 68];
    else if (t < 104) s_en1w[t - 72]  = en1_w[t - 72];
    else if (t < 112) s_en1b[t - 104] = en1_b[t - 104];
    else if (t < 128) s_en2b[t - 112] = en2_b[t - 112];
    else              s_en2w[t - 128] = en2_w[t - 128];
    s_en3w[t]       = en3_w[t];
    s_en3w[t + 256] = en3_w[t + 256];
    if (t >= 192 && t < 224) s_en3b[t - 192] = en3_b[t - 192];
    __syncthreads();

    const int lane = t & 31;
    const int w    = t >> 5;
    const int gwid = (blockIdx.x - PACK_BLOCKS) * 8 + w;
    if (gwid >= TAB_WARPS) return;
    const int tt = gwid / WARPS_PER_TT;
    const int wb = gwid % WARPS_PER_TT;

    // ---- every lane recomputes td/v8 from shared (pure ALU) ----
    float v8[8];
    {
        const float ti = (float)(tt >> 1);
        const float tj = (float)(tt & 1);
        float e4[4] = {0.f, 0.f, 0.f, 0.f};
        #pragma unroll
        for (int pass = 0; pass < 2; pass++) {
            const float a0 = pass ? tj : ti;
            const float a1 = pass ? ti : tj;
            float h[4];
            #pragma unroll
            for (int k = 0; k < 4; k++)
                h[k] = fmaxf(a0 * s_es1w[k] + a1 * s_es1w[4 + k] + s_es1b[k], 0.f);
            #pragma unroll
            for (int k = 0; k < 4; k++) {
                float aa = s_es2b[k];
                #pragma unroll
                for (int j = 0; j < 4; j++) aa += h[j] * s_es2w[j * 4 + k];
                e4[k] += aa;
            }
        }
        float y4[4];
        #pragma unroll
        for (int k = 0; k < 4; k++) {
            float aa = s_fs1b[k];
            #pragma unroll
            for (int j = 0; j < 4; j++) aa += e4[j] * s_fs1w[j * 4 + k];
            y4[k] = fmaxf(aa, 0.f);
        }
        float td[4];
        #pragma unroll
        for (int k = 0; k < 4; k++) {
            float aa = s_fs2b[k];
            #pragma unroll
            for (int j = 0; j < 4; j++) aa += y4[j] * s_fs2w[j * 4 + k];
            td[k] = aa;
        }
        #pragma unroll
        for (int o = 0; o < 8; o++) {
            float aa = 0.f;
            #pragma unroll
            for (int d = 0; d < 4; d++) aa += td[d] * s_en1w[d * 8 + o];
            v8[o] = aa;
        }
    }

    // ---- lane computes h2[16] at its endpoint ----
    const int e_id = min(wb * CPW + lane, CELLS);
    const float se = __uint_as_float((unsigned)(EBASE + e_id) << CSHIFT);
    {
        float h1[8];
        #pragma unroll
        for (int o = 0; o < 8; o++)
            h1[o] = fmaxf(fmaf(se, v8[o], s_en1b[o]), 0.f);
        #pragma unroll
        for (int c = 0; c < 16; c++) {
            float aa = s_en2b[c];
            #pragma unroll
            for (int j = 0; j < 8; j++)
                aa = fmaf(h1[j], s_en2w[j * 16 + c], aa);
            s_h2[w][lane][c] = fmaxf(aa, 0.f);
        }
    }
    __syncwarp();

    // ---- lane g sweeps endpoints, emits slope/intercept per cell ----
    const int g = lane;
    float2 W3f[8];
    #pragma unroll
    for (int q = 0; q < 8; q++) {
        W3f[q].x = s_en3w[(2 * q)     * 32 + g];
        W3f[q].y = s_en3w[(2 * q + 1) * 32 + g];
    }
    const unsigned long long b3g2 = pack2(s_en3b[g], 0.f);

    float Gp = 0.f, sp = 0.f;
    #pragma unroll 4
    for (int e2 = 0; e2 < 32; e2++) {
        const ulonglong2* hq = reinterpret_cast<const ulonglong2*>(s_h2[w][e2]);
        const ulonglong2 hA = hq[0];
        const ulonglong2 hB = hq[1];
        unsigned long long acc = b3g2;
        ffma2(acc, hA.x, *reinterpret_cast<const unsigned long long*>(&W3f[0]));
        ffma2(acc, hA.y, *reinterpret_cast<const unsigned long long*>(&W3f[1]));
        ffma2(acc, hB.x, *reinterpret_cast<const unsigned long long*>(&W3f[2]));
        ffma2(acc, hB.y, *reinterpret_cast<const unsigned long long*>(&W3f[3]));
        const ulonglong2 hC = hq[2];
        const ulonglong2 hD = hq[3];
        ffma2(acc, hC.x, *reinterpret_cast<const unsigned long long*>(&W3f[4]));
        ffma2(acc, hC.y, *reinterpret_cast<const unsigned long long*>(&W3f[5]));
        ffma2(acc, hD.x, *reinterpret_cast<const unsigned long long*>(&W3f[6]));
        ffma2(acc, hD.y, *reinterpret_cast<const unsigned long long*>(&W3f[7]));
        float glo, ghi;
        unpack2(acc, glo, ghi);
        const float Gc = glo + ghi;
        const float sc = __uint_as_float(
            (unsigned)(EBASE + min(wb * CPW + e2, CELLS)) << CSHIFT);

        const int cell = wb * CPW + e2 - 1;
        if (e2 > 0 && cell < CELLS) {
            const float slope = (Gc - Gp) / (sc - sp);
            g_tab[(tt * CELLS + cell) * 32 + g] =
                make_float2(slope, fmaf(-slope, sp, Gp));
        }
        Gp = Gc; sp = sc;
    }
}

// ---------------------------------------------------------------------------
// Main kernel: one warp per atom; compacted survivors + 8 zero-pad slots;
// phase 2 = blind 4-wide G lookup + FFMA2 (no clamps, no predicates).
// ---------------------------------------------------------------------------
__global__ __launch_bounds__(256, 4)
void descriptor_kernel(
    const int* __restrict__ neigh,   // [S,N,M]
    float*     __restrict__ out)     // [S,N,32,16]
{
    __shared__ float4 sh_rt[8][72];
    __shared__ int    sh_off[8][72];

    const int tid  = threadIdx.x;
    const int lane = tid & 31;
    const int w    = tid >> 5;

    const int atom = blockIdx.x * 8 + w;      // atom = s*N + n
    const int base = atom & ~4095;            // snapshot base (N = 4096)

    const float4 pi = g_pos4[atom];
    const int    ti2 = 2 * (int)pi.w;

    // -------- Phase 1: prefetch gathers, then geometry + compaction --------
    const int2 nb2 = reinterpret_cast<const int2*>(neigh + atom * M)[lane];
    const int jj0 = (nb2.x < 0) ? 0 : nb2.x;
    const int jj1 = (nb2.y < 0) ? 0 : nb2.y;
    const float4 pj0 = g_pos4[base + jj0];
    const float4 pj1 = g_pos4[base + jj1];

    int cnt = 0;
    #pragma unroll
    for (int p = 0; p < 2; p++) {
        const int    nb = (p == 0) ? nb2.x : nb2.y;
        const float4 pj = (p == 0) ? pj0 : pj1;

        float dx = pj.x - pi.x; dx -= 20.f * rintf(dx * 0.05f);
        float dy = pj.y - pi.y; dy -= 20.f * rintf(dy * 0.05f);
        float dz = pj.z - pi.z; dz -= 20.f * rintf(dz * 0.05f);

        const float r2   = fmaf(dx, dx, fmaf(dy, dy, fmaf(dz, dz, 1e-12f)));
        const float rinv = rsqrtf(r2);
        const float r    = r2 * rinv;

        float sw;
        if (r < 2.f)      sw = 1.f;
        else if (r < 6.f) sw = fmaf(0.5f, cospif((r - 2.f) * 0.25f), 0.5f);
        else              sw = 0.f;

        const float s_ij  = (nb < 0) ? 0.f : sw * rinv;
        const float srinv = s_ij * rinv;

        const bool alive = (s_ij != 0.f);
        const unsigned bb = __ballot_sync(FULL, alive);
        if (alive) {
            const int tt = ti2 + (int)pj.w;
            int c = (int)(__float_as_uint(s_ij) >> CSHIFT) - EBASE;
            c = max(min(c, CELLS - 1), 0);
            const int pos = cnt + __popc(bb & ((1u << lane) - 1u));
            sh_off[w][pos] = (tt * CELLS + c) << 8;   // byte offset of row
            sh_rt[w][pos] = make_float4(s_ij, dx * srinv, dy * srinv, dz * srinv);
        }
        cnt += __popc(bb);
    }
    // 8 zero-pad slots: s=0, row 0 -> contribution is exactly 0
    if (lane < 8) {
        sh_rt[w][cnt + lane] = make_float4(0.f, 0.f, 0.f, 0.f);
        sh_off[w][cnt + lane] = 0;
    }
    __syncwarp();

    unsigned long long A01 = 0ull, A23 = 0ull;   // (A0,A1),(A2,A3)

    // -------- Phase 2: blind 4-wide table-lookup pipeline --------
    if (cnt > 0) {
        const char* tabc = reinterpret_cast<const char*>(g_tab);
        float  ss[4];
        float2 si[4];
        #pragma unroll
        for (int j = 0; j < 4; j++) {
            ss[j] = sh_rt[w][j].x;
            si[j] = __ldg(reinterpret_cast<const float2*>(
                              tabc + sh_off[w][j]) + lane);
        }

        for (int i = 0; i < cnt; i += 4) {
            const bool more = (i + 4 < cnt);   // warp-uniform
            float  ns[4];
            float2 nsi[4];
            if (more) {
                #pragma unroll
                for (int j = 0; j < 4; j++) {
                    ns[j] = sh_rt[w][i + 4 + j].x;
                    nsi[j] = __ldg(reinterpret_cast<const float2*>(
                                       tabc + sh_off[w][i + 4 + j]) + lane);
                }
            }

            #pragma unroll
            for (int j = 0; j < 4; j++) {
                const float G = fmaf(si[j].x, ss[j], si[j].y);
                const unsigned long long G2 = pack2(G, G);
                const ulonglong2 rt2 =
                    *reinterpret_cast<const ulonglong2*>(&sh_rt[w][i + j]);
                ffma2(A01, G2, rt2.x);
                ffma2(A23, G2, rt2.y);
            }
            if (more) {
                #pragma unroll
                for (int j = 0; j < 4; j++) { ss[j] = ns[j]; si[j] = nsi[j]; }
            }
        }
    }

    // -------- Epilogue: D[g][k] = sum_d A[g][d]*A[k][d], k < 16 ------------
    float a0, a1, a2, a3;
    unpack2(A01, a0, a1);
    unpack2(A23, a2, a3);

    float* shT = reinterpret_cast<float*>(&sh_rt[w][0]);
    __syncwarp();
    shT[0 * 32 + lane] = a0;
    shT[1 * 32 + lane] = a1;
    shT[2 * 32 + lane] = a2;
    shT[3 * 32 + lane] = a3;
    __syncwarp();

    const unsigned long long d0 = pack2(a0, a0);
    const unsigned long long d1 = pack2(a1, a1);
    const unsigned long long d2 = pack2(a2, a2);
    const unsigned long long d3 = pack2(a3, a3);

    float4* o4 = reinterpret_cast<float4*>(out + (size_t)atom * 512 + lane * 16);
    #pragma unroll
    for (int kg = 0; kg < 4; kg++) {
        const int k0 = kg * 4;
        const ulonglong2 r0 = *reinterpret_cast<const ulonglong2*>(&shT[0 * 32 + k0]);
        const ulonglong2 r1 = *reinterpret_cast<const ulonglong2*>(&shT[1 * 32 + k0]);
        const ulonglong2 r2 = *reinterpret_cast<const ulonglong2*>(&shT[2 * 32 + k0]);
        const ulonglong2 r3 = *reinterpret_cast<const ulonglong2*>(&shT[3 * 32 + k0]);

        unsigned long long accA = mul2(d0, r0.x);   // (d[k0], d[k0+1])
        unsigned long long accB = mul2(d0, r0.y);   // (d[k0+2], d[k0+3])
        ffma2(accA, d1, r1.x);  ffma2(accB, d1, r1.y);
        ffma2(accA, d2, r2.x);  ffma2(accB, d2, r2.y);
        ffma2(accA, d3, r3.x);  ffma2(accB, d3, r3.y);

        float4 res;
        unpack2(accA, res.x, res.y);
        unpack2(accB, res.z, res.w);
        o4[kg] = res;
    }
}

// ---------------------------------------------------------------------------
extern "C" void kernel_launch(void* const* d_in, const int* in_sizes, int n_in,
                              void* d_out, int out_size)
{
    const float* inputs      = (const float*)d_in[0];
    const int*   input_types = (const int*)  d_in[1];
    const int*   neigh_list  = (const int*)  d_in[2];
    const float* es1_w = (const float*)d_in[3];
    const float* es1_b = (const float*)d_in[4];
    const float* es2_w = (const float*)d_in[5];
    const float* es2_b = (const float*)d_in[6];
    const float* fs1_w = (const float*)d_in[7];
    const float* fs1_b = (const float*)d_in[8];
    const float* fs2_w = (const float*)d_in[9];
    const float* fs2_b = (const float*)d_in[10];
    const float* en1_w = (const float*)d_in[11];
    const float* en1_b = (const float*)d_in[12];
    const float* en2_w = (const float*)d_in[13];
    const float* en2_b = (const float*)d_in[14];
    const float* en3_w = (const float*)d_in[15];
    const float* en3_b = (const float*)d_in[16];
    float* out = (float*)d_out;

    prep_kernel<<<PACK_BLOCKS + TAB_BLOCKS, 256>>>(
        inputs, input_types,
        es1_w, es1_b, es2_w, es2_b,
        fs1_w, fs1_b, fs2_w, fs2_b,
        en1_w, en1_b, en2_w, en2_b, en3_w, en3_b);

    descriptor_kernel<<<SN / 8, 256>>>(neigh_list, out);
}

// round 14
// speedup vs baseline: 1.0752x; 1.0752x over previous
#include <cuda_runtime.h>
#include <cstdint>

#define FULL 0xffffffffu

static constexpr int S = 8;
static constexpr int N = 4096;
static constexpr int M = 64;
static constexpr int SN = S * N;

static constexpr int CPO   = 32;                  // cells per octave
static constexpr int CELLS = 17 * CPO;            // 544
static constexpr int EBASE = (127 - 12) * CPO;    // s_min = 2^-12
static constexpr int CSHIFT = 18;                 // 23 - log2(CPO)
static constexpr int PACK_BLOCKS = SN / 4 / 256;  // 32
static constexpr int CPW = 31;                    // cells per warp
static constexpr int WARPS_PER_TT = (CELLS + CPW - 1) / CPW;   // 18
static constexpr int TAB_WARPS = 4 * WARPS_PER_TT;             // 72
static constexpr int TAB_BLOCKS = (TAB_WARPS + 7) / 8;         // 9

__device__ float4 g_pos4[SN];             // (x, y, z, type)
__device__ float2 g_tab[4 * CELLS * 32];  // (slope, intercept)[tt][cell][g]

// ---------------- packed f32x2 helpers (sm_103a FFMA2) ----------------
__device__ __forceinline__ void ffma2(unsigned long long& d,
                                      unsigned long long a,
                                      unsigned long long b) {
    asm("fma.rn.f32x2 %0, %1, %2, %0;" : "+l"(d) : "l"(a), "l"(b));
}
__device__ __forceinline__ unsigned long long mul2(unsigned long long a,
                                                   unsigned long long b) {
    unsigned long long d;
    asm("mul.rn.f32x2 %0, %1, %2;" : "=l"(d) : "l"(a), "l"(b));
    return d;
}
__device__ __forceinline__ unsigned long long pack2(float lo, float hi) {
    unsigned long long d;
    asm("mov.b64 %0, {%1, %2};" : "=l"(d) : "f"(lo), "f"(hi));
    return d;
}
__device__ __forceinline__ void unpack2(unsigned long long v,
                                        float& lo, float& hi) {
    asm("mov.b64 {%0, %1}, %2;" : "=f"(lo), "=f"(hi) : "l"(v));
}

// ---------------------------------------------------------------------------
// Prep kernel.
//  blocks [0, PACK_BLOCKS): pack positions+type into float4 (vectorized)
//  blocks [PACK_BLOCKS, +TAB_BLOCKS): PWL table build (small: 544 cells/tt).
// ---------------------------------------------------------------------------
__global__ void prep_kernel(
    const float* __restrict__ pos, const int* __restrict__ types,
    const float* __restrict__ es1_w, const float* __restrict__ es1_b,
    const float* __restrict__ es2_w, const float* __restrict__ es2_b,
    const float* __restrict__ fs1_w, const float* __restrict__ fs1_b,
    const float* __restrict__ fs2_w, const float* __restrict__ fs2_b,
    const float* __restrict__ en1_w, const float* __restrict__ en1_b,
    const float* __restrict__ en2_w, const float* __restrict__ en2_b,
    const float* __restrict__ en3_w, const float* __restrict__ en3_b)
{
    if (blockIdx.x < PACK_BLOCKS) {
        const int idx = blockIdx.x * blockDim.x + threadIdx.x;
        const float4* pv = reinterpret_cast<const float4*>(pos) + idx * 3;
        const float4 a = pv[0], b = pv[1], c = pv[2];
        const int4 t = reinterpret_cast<const int4*>(types)[idx];
        float4* o = g_pos4 + idx * 4;
        o[0] = make_float4(a.x, a.y, a.z, (float)t.x);
        o[1] = make_float4(a.w, b.x, b.y, (float)t.y);
        o[2] = make_float4(b.z, b.w, c.x, (float)t.z);
        o[3] = make_float4(c.y, c.z, c.w, (float)t.w);
        return;
    }

    __shared__ float s_es1w[8],  s_es1b[4],  s_es2w[16], s_es2b[4];
    __shared__ float s_fs1w[16], s_fs1b[4],  s_fs2w[16], s_fs2b[4];
    __shared__ float s_en1w[32], s_en1b[8],  s_en2w[128], s_en2b[16];
    __shared__ float s_en3w[512], s_en3b[32];
    __shared__ float s_h2[8][32][16];

    const int t = threadIdx.x;
    // ---- one parallel load round: disjoint thread ranges ----
    if      (t < 8)   s_es1w[t]       = es1_w[t];
    else if (t < 12)  s_es1b[t - 8]   = es1_b[t - 8];
    else if (t < 28)  s_es2w[t - 12]  = es2_w[t - 12];
    else if (t < 32)  s_es2b[t - 28]  = es2_b[t - 28];
    else if (t < 48)  s_fs1w[t - 32]  = fs1_w[t - 32];
    else if (t < 52)  s_fs1b[t - 48]  = fs1_b[t - 48];
    else if (t < 68)  s_fs2w[t - 52]  = fs2_w[t - 52];
    else if (t < 72)  s_fs2b[t - 68]  = fs2_b[t - 68];
    else if (t < 104) s_en1w[t - 72]  = en1_w[t - 72];
    else if (t < 112) s_en1b[t - 104] = en1_b[t - 104];
    else if (t < 128) s_en2b[t - 112] = en2_b[t - 112];
    else              s_en2w[t - 128] = en2_w[t - 128];
    s_en3w[t]       = en3_w[t];
    s_en3w[t + 256] = en3_w[t + 256];
    if (t >= 192 && t < 224) s_en3b[t - 192] = en3_b[t - 192];
    __syncthreads();

    const int lane = t & 31;
    const int w    = t >> 5;
    const int gwid = (blockIdx.x - PACK_BLOCKS) * 8 + w;
    if (gwid >= TAB_WARPS) return;
    const int tt = gwid / WARPS_PER_TT;
    const int wb = gwid % WARPS_PER_TT;

    // ---- every lane recomputes td/v8 from shared (pure ALU) ----
    float v8[8];
    {
        const float ti = (float)(tt >> 1);
        const float tj = (float)(tt & 1);
        float e4[4] = {0.f, 0.f, 0.f, 0.f};
        #pragma unroll
        for (int pass = 0; pass < 2; pass++) {
            const float a0 = pass ? tj : ti;
            const float a1 = pass ? ti : tj;
            float h[4];
            #pragma unroll
            for (int k = 0; k < 4; k++)
                h[k] = fmaxf(a0 * s_es1w[k] + a1 * s_es1w[4 + k] + s_es1b[k], 0.f);
            #pragma unroll
            for (int k = 0; k < 4; k++) {
                float aa = s_es2b[k];
                #pragma unroll
                for (int j = 0; j < 4; j++) aa += h[j] * s_es2w[j * 4 + k];
                e4[k] += aa;
            }
        }
        float y4[4];
        #pragma unroll
        for (int k = 0; k < 4; k++) {
            float aa = s_fs1b[k];
            #pragma unroll
            for (int j = 0; j < 4; j++) aa += e4[j] * s_fs1w[j * 4 + k];
            y4[k] = fmaxf(aa, 0.f);
        }
        float td[4];
        #pragma unroll
        for (int k = 0; k < 4; k++) {
            float aa = s_fs2b[k];
            #pragma unroll
            for (int j = 0; j < 4; j++) aa += y4[j] * s_fs2w[j * 4 + k];
            td[k] = aa;
        }
        #pragma unroll
        for (int o = 0; o < 8; o++) {
            float aa = 0.f;
            #pragma unroll
            for (int d = 0; d < 4; d++) aa += td[d] * s_en1w[d * 8 + o];
            v8[o] = aa;
        }
    }

    // ---- lane computes h2[16] at its endpoint ----
    const int e_id = min(wb * CPW + lane, CELLS);
    const float se = __uint_as_float((unsigned)(EBASE + e_id) << CSHIFT);
    {
        float h1[8];
        #pragma unroll
        for (int o = 0; o < 8; o++)
            h1[o] = fmaxf(fmaf(se, v8[o], s_en1b[o]), 0.f);
        #pragma unroll
        for (int c = 0; c < 16; c++) {
            float aa = s_en2b[c];
            #pragma unroll
            for (int j = 0; j < 8; j++)
                aa = fmaf(h1[j], s_en2w[j * 16 + c], aa);
            s_h2[w][lane][c] = fmaxf(aa, 0.f);
        }
    }
    __syncwarp();

    // ---- lane g sweeps endpoints, emits slope/intercept per cell ----
    const int g = lane;
    float2 W3f[8];
    #pragma unroll
    for (int q = 0; q < 8; q++) {
        W3f[q].x = s_en3w[(2 * q)     * 32 + g];
        W3f[q].y = s_en3w[(2 * q + 1) * 32 + g];
    }
    const unsigned long long b3g2 = pack2(s_en3b[g], 0.f);

    float Gp = 0.f, sp = 0.f;
    #pragma unroll 4
    for (int e2 = 0; e2 < 32; e2++) {
        const ulonglong2* hq = reinterpret_cast<const ulonglong2*>(s_h2[w][e2]);
        const ulonglong2 hA = hq[0];
        const ulonglong2 hB = hq[1];
        unsigned long long acc = b3g2;
        ffma2(acc, hA.x, *reinterpret_cast<const unsigned long long*>(&W3f[0]));
        ffma2(acc, hA.y, *reinterpret_cast<const unsigned long long*>(&W3f[1]));
        ffma2(acc, hB.x, *reinterpret_cast<const unsigned long long*>(&W3f[2]));
        ffma2(acc, hB.y, *reinterpret_cast<const unsigned long long*>(&W3f[3]));
        const ulonglong2 hC = hq[2];
        const ulonglong2 hD = hq[3];
        ffma2(acc, hC.x, *reinterpret_cast<const unsigned long long*>(&W3f[4]));
        ffma2(acc, hC.y, *reinterpret_cast<const unsigned long long*>(&W3f[5]));
        ffma2(acc, hD.x, *reinterpret_cast<const unsigned long long*>(&W3f[6]));
        ffma2(acc, hD.y, *reinterpret_cast<const unsigned long long*>(&W3f[7]));
        float glo, ghi;
        unpack2(acc, glo, ghi);
        const float Gc = glo + ghi;
        const float sc = __uint_as_float(
            (unsigned)(EBASE + min(wb * CPW + e2, CELLS)) << CSHIFT);

        const int cell = wb * CPW + e2 - 1;
        if (e2 > 0 && cell < CELLS) {
            const float slope = (Gc - Gp) / (sc - sp);
            g_tab[(tt * CELLS + cell) * 32 + g] =
                make_float2(slope, fmaf(-slope, sp, Gp));
        }
        Gp = Gc; sp = sc;
    }
}

// ---------------------------------------------------------------------------
// Main kernel: one warp per atom; compacted survivors + 8 zero-pad slots;
// phase 2 = blind 4-wide G lookup + FFMA2 (no clamps, no predicates).
// ---------------------------------------------------------------------------
__global__ __launch_bounds__(256, 4)
void descriptor_kernel(
    const int* __restrict__ neigh,   // [S,N,M]
    float*     __restrict__ out)     // [S,N,32,16]
{
    __shared__ float4 sh_rt[8][72];
    __shared__ int    sh_off[8][72];

    const int tid  = threadIdx.x;
    const int lane = tid & 31;
    const int w    = tid >> 5;

    const int atom = blockIdx.x * 8 + w;      // atom = s*N + n
    const int base = atom & ~4095;            // snapshot base (N = 4096)

    const float4 pi = g_pos4[atom];
    const int    ti2 = 2 * (int)pi.w;

    // -------- Phase 1: prefetch gathers, then geometry + compaction --------
    const int2 nb2 = reinterpret_cast<const int2*>(neigh + atom * M)[lane];
    const int jj0 = (nb2.x < 0) ? 0 : nb2.x;
    const int jj1 = (nb2.y < 0) ? 0 : nb2.y;
    const float4 pj0 = g_pos4[base + jj0];
    const float4 pj1 = g_pos4[base + jj1];

    int cnt = 0;
    #pragma unroll
    for (int p = 0; p < 2; p++) {
        const int    nb = (p == 0) ? nb2.x : nb2.y;
        const float4 pj = (p == 0) ? pj0 : pj1;

        float dx = pj.x - pi.x; dx -= 20.f * rintf(dx * 0.05f);
        float dy = pj.y - pi.y; dy -= 20.f * rintf(dy * 0.05f);
        float dz = pj.z - pi.z; dz -= 20.f * rintf(dz * 0.05f);

        const float r2   = fmaf(dx, dx, fmaf(dy, dy, fmaf(dz, dz, 1e-12f)));
        const float rinv = rsqrtf(r2);
        const float r    = r2 * rinv;

        float sw;
        if (r < 2.f)      sw = 1.f;
        else if (r < 6.f) sw = fmaf(0.5f, cospif((r - 2.f) * 0.25f), 0.5f);
        else              sw = 0.f;

        const float s_ij  = (nb < 0) ? 0.f : sw * rinv;
        const float srinv = s_ij * rinv;

        const bool alive = (s_ij != 0.f);
        const unsigned bb = __ballot_sync(FULL, alive);
        if (alive) {
            const int tt = ti2 + (int)pj.w;
            int c = (int)(__float_as_uint(s_ij) >> CSHIFT) - EBASE;
            c = max(min(c, CELLS - 1), 0);
            const int pos = cnt + __popc(bb & ((1u << lane) - 1u));
            sh_off[w][pos] = (tt * CELLS + c) << 8;   // byte offset of row
            sh_rt[w][pos] = make_float4(s_ij, dx * srinv, dy * srinv, dz * srinv);
        }
        cnt += __popc(bb);
    }
    // 8 zero-pad slots: s=0, row 0 -> contribution is exactly 0
    if (lane < 8) {
        sh_rt[w][cnt + lane] = make_float4(0.f, 0.f, 0.f, 0.f);
        sh_off[w][cnt + lane] = 0;
    }
    __syncwarp();

    unsigned long long A01 = 0ull, A23 = 0ull;   // (A0,A1),(A2,A3)

    // -------- Phase 2: blind 4-wide table-lookup pipeline --------
    if (cnt > 0) {
        const char* tabc = reinterpret_cast<const char*>(g_tab);
        float  ss[4];
        float2 si[4];
        #pragma unroll
        for (int j = 0; j < 4; j++) {
            ss[j] = sh_rt[w][j].x;
            si[j] = __ldg(reinterpret_cast<const float2*>(
                              tabc + sh_off[w][j]) + lane);
        }

        for (int i = 0; i < cnt; i += 4) {
            const bool more = (i + 4 < cnt);   // warp-uniform
            float  ns[4];
            float2 nsi[4];
            if (more) {
                #pragma unroll
                for (int j = 0; j < 4; j++) {
                    ns[j] = sh_rt[w][i + 4 + j].x;
                    nsi[j] = __ldg(reinterpret_cast<const float2*>(
                                       tabc + sh_off[w][i + 4 + j]) + lane);
                }
            }

            #pragma unroll
            for (int j = 0; j < 4; j++) {
                const float G = fmaf(si[j].x, ss[j], si[j].y);
                const unsigned long long G2 = pack2(G, G);
                const ulonglong2 rt2 =
                    *reinterpret_cast<const ulonglong2*>(&sh_rt[w][i + j]);
                ffma2(A01, G2, rt2.x);
                ffma2(A23, G2, rt2.y);
            }
            if (more) {
                #pragma unroll
                for (int j = 0; j < 4; j++) { ss[j] = ns[j]; si[j] = nsi[j]; }
            }
        }
    }

    // -------- Epilogue: D[g][k] = sum_d A[g][d]*A[k][d], k < 16 ------------
    float a0, a1, a2, a3;
    unpack2(A01, a0, a1);
    unpack2(A23, a2, a3);

    float* shT = reinterpret_cast<float*>(&sh_rt[w][0]);
    __syncwarp();
    shT[0 * 32 + lane] = a0;
    shT[1 * 32 + lane] = a1;
    shT[2 * 32 + lane] = a2;
    shT[3 * 32 + lane] = a3;
    __syncwarp();

    const unsigned long long d0 = pack2(a0, a0);
    const unsigned long long d1 = pack2(a1, a1);
    const unsigned long long d2 = pack2(a2, a2);
    const unsigned long long d3 = pack2(a3, a3);

    float4* o4 = reinterpret_cast<float4*>(out + (size_t)atom * 512 + lane * 16);
    #pragma unroll
    for (int kg = 0; kg < 4; kg++) {
        const int k0 = kg * 4;
        const ulonglong2 r0 = *reinterpret_cast<const ulonglong2*>(&shT[0 * 32 + k0]);
        const ulonglong2 r1 = *reinterpret_cast<const ulonglong2*>(&shT[1 * 32 + k0]);
        const ulonglong2 r2 = *reinterpret_cast<const ulonglong2*>(&shT[2 * 32 + k0]);
        const ulonglong2 r3 = *reinterpret_cast<const ulonglong2*>(&shT[3 * 32 + k0]);

        unsigned long long accA = mul2(d0, r0.x);   // (d[k0], d[k0+1])
        unsigned long long accB = mul2(d0, r0.y);   // (d[k0+2], d[k0+3])
        ffma2(accA, d1, r1.x);  ffma2(accB, d1, r1.y);
        ffma2(accA, d2, r2.x);  ffma2(accB, d2, r2.y);
        ffma2(accA, d3, r3.x);  ffma2(accB, d3, r3.y);

        float4 res;
        unpack2(accA, res.x, res.y);
        unpack2(accB, res.z, res.w);
        o4[kg] = res;
    }
}

// ---------------------------------------------------------------------------
extern "C" void kernel_launch(void* const* d_in, const int* in_sizes, int n_in,
                              void* d_out, int out_size)
{
    const float* inputs      = (const float*)d_in[0];
    const int*   input_types = (const int*)  d_in[1];
    const int*   neigh_list  = (const int*)  d_in[2];
    const float* es1_w = (const float*)d_in[3];
    const float* es1_b = (const float*)d_in[4];
    const float* es2_w = (const float*)d_in[5];
    const float* es2_b = (const float*)d_in[6];
    const float* fs1_w = (const float*)d_in[7];
    const float* fs1_b = (const float*)d_in[8];
    const float* fs2_w = (const float*)d_in[9];
    const float* fs2_b = (const float*)d_in[10];
    const float* en1_w = (const float*)d_in[11];
    const float* en1_b = (const float*)d_in[12];
    const float* en2_w = (const float*)d_in[13];
    const float* en2_b = (const float*)d_in[14];
    const float* en3_w = (const float*)d_in[15];
    const float* en3_b = (const float*)d_in[16];
    float* out = (float*)d_out;

    prep_kernel<<<PACK_BLOCKS + TAB_BLOCKS, 256>>>(
        inputs, input_types,
        es1_w, es1_b, es2_w, es2_b,
        fs1_w, fs1_b, fs2_w, fs2_b,
        en1_w, en1_b, en2_w, en2_b, en3_w, en3_b);

    descriptor_kernel<<<SN / 8, 256>>>(neigh_list, out);
}

// round 15
// speedup vs baseline: 1.1923x; 1.1089x over previous
#include <cuda_runtime.h>
#include <cstdint>

#define FULL 0xffffffffu

static constexpr int S = 8;
static constexpr int N = 4096;
static constexpr int M = 64;
static constexpr int SN = S * N;

static constexpr int CPO   = 32;                  // cells per octave
static constexpr int CELLS = 17 * CPO;            // 544
static constexpr int EBASE = (127 - 12) * CPO;    // s_min = 2^-12
static constexpr int CSHIFT = 18;                 // 23 - log2(CPO)
static constexpr int PACK_BLOCKS = SN / 4 / 256;  // 32
static constexpr int CPW = 7;                     // cells per warp (short sweep)
static constexpr int WARPS_PER_TT = (CELLS + CPW - 1) / CPW;   // 78
static constexpr int TAB_WARPS = 4 * WARPS_PER_TT;             // 312
static constexpr int TAB_BLOCKS = (TAB_WARPS + 7) / 8;         // 39

__device__ float4 g_pos4[SN];             // (x, y, z, type)
__device__ float2 g_tab[4 * CELLS * 32];  // (slope, intercept)[tt][cell][g]

// ---------------- packed f32x2 helpers (sm_103a FFMA2) ----------------
__device__ __forceinline__ void ffma2(unsigned long long& d,
                                      unsigned long long a,
                                      unsigned long long b) {
    asm("fma.rn.f32x2 %0, %1, %2, %0;" : "+l"(d) : "l"(a), "l"(b));
}
__device__ __forceinline__ unsigned long long mul2(unsigned long long a,
                                                   unsigned long long b) {
    unsigned long long d;
    asm("mul.rn.f32x2 %0, %1, %2;" : "=l"(d) : "l"(a), "l"(b));
    return d;
}
__device__ __forceinline__ unsigned long long pack2(float lo, float hi) {
    unsigned long long d;
    asm("mov.b64 %0, {%1, %2};" : "=l"(d) : "f"(lo), "f"(hi));
    return d;
}
__device__ __forceinline__ void unpack2(unsigned long long v,
                                        float& lo, float& hi) {
    asm("mov.b64 {%0, %1}, %2;" : "=f"(lo), "=f"(hi) : "l"(v));
}

// ---------------------------------------------------------------------------
// Prep kernel.
//  blocks [0, PACK_BLOCKS): pack positions+type into float4 (vectorized)
//  blocks [PACK_BLOCKS, +TAB_BLOCKS): PWL table build, short 7-cell sweeps.
// ---------------------------------------------------------------------------
__global__ void prep_kernel(
    const float* __restrict__ pos, const int* __restrict__ types,
    const float* __restrict__ es1_w, const float* __restrict__ es1_b,
    const float* __restrict__ es2_w, const float* __restrict__ es2_b,
    const float* __restrict__ fs1_w, const float* __restrict__ fs1_b,
    const float* __restrict__ fs2_w, const float* __restrict__ fs2_b,
    const float* __restrict__ en1_w, const float* __restrict__ en1_b,
    const float* __restrict__ en2_w, const float* __restrict__ en2_b,
    const float* __restrict__ en3_w, const float* __restrict__ en3_b)
{
    if (blockIdx.x < PACK_BLOCKS) {
        const int idx = blockIdx.x * blockDim.x + threadIdx.x;
        const float4* pv = reinterpret_cast<const float4*>(pos) + idx * 3;
        const float4 a = pv[0], b = pv[1], c = pv[2];
        const int4 t = reinterpret_cast<const int4*>(types)[idx];
        float4* o = g_pos4 + idx * 4;
        o[0] = make_float4(a.x, a.y, a.z, (float)t.x);
        o[1] = make_float4(a.w, b.x, b.y, (float)t.y);
        o[2] = make_float4(b.z, b.w, c.x, (float)t.z);
        o[3] = make_float4(c.y, c.z, c.w, (float)t.w);
        return;
    }

    __shared__ float s_es1w[8],  s_es1b[4],  s_es2w[16], s_es2b[4];
    __shared__ float s_fs1w[16], s_fs1b[4],  s_fs2w[16], s_fs2b[4];
    __shared__ float s_en1w[32], s_en1b[8],  s_en2w[128], s_en2b[16];
    __shared__ float s_en3w[512], s_en3b[32];
    __shared__ float s_h2[8][8][16];

    const int t = threadIdx.x;
    // ---- one parallel load round: disjoint thread ranges ----
    if      (t < 8)   s_es1w[t]       = es1_w[t];
    else if (t < 12)  s_es1b[t - 8]   = es1_b[t - 8];
    else if (t < 28)  s_es2w[t - 12]  = es2_w[t - 12];
    else if (t < 32)  s_es2b[t - 28]  = es2_b[t - 28];
    else if (t < 48)  s_fs1w[t - 32]  = fs1_w[t - 32];
    else if (t < 52)  s_fs1b[t - 48]  = fs1_b[t - 48];
    else if (t < 68)  s_fs2w[t - 52]  = fs2_w[t - 52];
    else if (t < 72)  s_fs2b[t - 68]  = fs2_b[t - 68];
    else if (t < 104) s_en1w[t - 72]  = en1_w[t - 72];
    else if (t < 112) s_en1b[t - 104] = en1_b[t - 104];
    else if (t < 128) s_en2b[t - 112] = en2_b[t - 112];
    else              s_en2w[t - 128] = en2_w[t - 128];
    s_en3w[t]       = en3_w[t];
    s_en3w[t + 256] = en3_w[t + 256];
    if (t >= 192 && t < 224) s_en3b[t - 192] = en3_b[t - 192];
    __syncthreads();

    const int lane = t & 31;
    const int w    = t >> 5;
    const int gwid = (blockIdx.x - PACK_BLOCKS) * 8 + w;
    if (gwid >= TAB_WARPS) return;
    const int tt = gwid / WARPS_PER_TT;
    const int wb = gwid % WARPS_PER_TT;

    // ---- every lane recomputes td/v8 from shared (pure ALU) ----
    float v8[8];
    {
        const float ti = (float)(tt >> 1);
        const float tj = (float)(tt & 1);
        float e4[4] = {0.f, 0.f, 0.f, 0.f};
        #pragma unroll
        for (int pass = 0; pass < 2; pass++) {
            const float a0 = pass ? tj : ti;
            const float a1 = pass ? ti : tj;
            float h[4];
            #pragma unroll
            for (int k = 0; k < 4; k++)
                h[k] = fmaxf(a0 * s_es1w[k] + a1 * s_es1w[4 + k] + s_es1b[k], 0.f);
            #pragma unroll
            for (int k = 0; k < 4; k++) {
                float aa = s_es2b[k];
                #pragma unroll
                for (int j = 0; j < 4; j++) aa += h[j] * s_es2w[j * 4 + k];
                e4[k] += aa;
            }
        }
        float y4[4];
        #pragma unroll
        for (int k = 0; k < 4; k++) {
            float aa = s_fs1b[k];
            #pragma unroll
            for (int j = 0; j < 4; j++) aa += e4[j] * s_fs1w[j * 4 + k];
            y4[k] = fmaxf(aa, 0.f);
        }
        float td[4];
        #pragma unroll
        for (int k = 0; k < 4; k++) {
            float aa = s_fs2b[k];
            #pragma unroll
            for (int j = 0; j < 4; j++) aa += y4[j] * s_fs2w[j * 4 + k];
            td[k] = aa;
        }
        #pragma unroll
        for (int o = 0; o < 8; o++) {
            float aa = 0.f;
            #pragma unroll
            for (int d = 0; d < 4; d++) aa += td[d] * s_en1w[d * 8 + o];
            v8[o] = aa;
        }
    }

    // ---- lanes 0-7 compute h2[16] at their endpoint ----
    if (lane < 8) {
        const int e_id = min(wb * CPW + lane, CELLS);
        const float se = __uint_as_float((unsigned)(EBASE + e_id) << CSHIFT);
        float h1[8];
        #pragma unroll
        for (int o = 0; o < 8; o++)
            h1[o] = fmaxf(fmaf(se, v8[o], s_en1b[o]), 0.f);
        #pragma unroll
        for (int c = 0; c < 16; c++) {
            float aa = s_en2b[c];
            #pragma unroll
            for (int j = 0; j < 8; j++)
                aa = fmaf(h1[j], s_en2w[j * 16 + c], aa);
            s_h2[w][lane][c] = fmaxf(aa, 0.f);
        }
    }
    __syncwarp();

    // ---- lane g sweeps 8 endpoints, emits slope/intercept per cell ----
    const int g = lane;
    float2 W3f[8];
    #pragma unroll
    for (int q = 0; q < 8; q++) {
        W3f[q].x = s_en3w[(2 * q)     * 32 + g];
        W3f[q].y = s_en3w[(2 * q + 1) * 32 + g];
    }
    const unsigned long long b3g2 = pack2(s_en3b[g], 0.f);

    float Gp = 0.f, sp = 0.f;
    #pragma unroll
    for (int e2 = 0; e2 < 8; e2++) {
        const ulonglong2* hq = reinterpret_cast<const ulonglong2*>(s_h2[w][e2]);
        const ulonglong2 hA = hq[0];
        const ulonglong2 hB = hq[1];
        unsigned long long acc = b3g2;
        ffma2(acc, hA.x, *reinterpret_cast<const unsigned long long*>(&W3f[0]));
        ffma2(acc, hA.y, *reinterpret_cast<const unsigned long long*>(&W3f[1]));
        ffma2(acc, hB.x, *reinterpret_cast<const unsigned long long*>(&W3f[2]));
        ffma2(acc, hB.y, *reinterpret_cast<const unsigned long long*>(&W3f[3]));
        const ulonglong2 hC = hq[2];
        const ulonglong2 hD = hq[3];
        ffma2(acc, hC.x, *reinterpret_cast<const unsigned long long*>(&W3f[4]));
        ffma2(acc, hC.y, *reinterpret_cast<const unsigned long long*>(&W3f[5]));
        ffma2(acc, hD.x, *reinterpret_cast<const unsigned long long*>(&W3f[6]));
        ffma2(acc, hD.y, *reinterpret_cast<const unsigned long long*>(&W3f[7]));
        float glo, ghi;
        unpack2(acc, glo, ghi);
        const float Gc = glo + ghi;
        const float sc = __uint_as_float(
            (unsigned)(EBASE + min(wb * CPW + e2, CELLS)) << CSHIFT);

        const int cell = wb * CPW + e2 - 1;
        if (e2 > 0 && cell < CELLS) {
            const float slope = (Gc - Gp) / (sc - sp);
            g_tab[(tt * CELLS + cell) * 32 + g] =
                make_float2(slope, fmaf(-slope, sp, Gp));
        }
        Gp = Gc; sp = sc;
    }
}

// ---------------------------------------------------------------------------
// Main kernel: one warp per atom; compacted survivors, tt in s mantissa LSBs;
// table offset recomputed in phase-2 prefetch (ALU, not shared);
// blind 4-wide G lookup + FFMA2.
// ---------------------------------------------------------------------------
__global__ __launch_bounds__(256, 4)
void descriptor_kernel(
    const int* __restrict__ neigh,   // [S,N,M]
    float*     __restrict__ out)     // [S,N,32,16]
{
    __shared__ float4 sh_rt[8][68];

    const int tid  = threadIdx.x;
    const int lane = tid & 31;
    const int w    = tid >> 5;

    const int atom = blockIdx.x * 8 + w;      // atom = s*N + n
    const int base = atom & ~4095;            // snapshot base (N = 4096)

    const float4 pi = g_pos4[atom];
    const int    ti2 = 2 * (int)pi.w;

    // -------- Phase 1: prefetch gathers, then geometry + compaction --------
    const int2 nb2 = reinterpret_cast<const int2*>(neigh + atom * M)[lane];
    const int jj0 = (nb2.x < 0) ? 0 : nb2.x;
    const int jj1 = (nb2.y < 0) ? 0 : nb2.y;
    const float4 pj0 = g_pos4[base + jj0];
    const float4 pj1 = g_pos4[base + jj1];

    int cnt = 0;
    #pragma unroll
    for (int p = 0; p < 2; p++) {
        const int    nb = (p == 0) ? nb2.x : nb2.y;
        const float4 pj = (p == 0) ? pj0 : pj1;

        float dx = pj.x - pi.x; dx -= 20.f * rintf(dx * 0.05f);
        float dy = pj.y - pi.y; dy -= 20.f * rintf(dy * 0.05f);
        float dz = pj.z - pi.z; dz -= 20.f * rintf(dz * 0.05f);

        const float r2   = fmaf(dx, dx, fmaf(dy, dy, fmaf(dz, dz, 1e-12f)));
        const float rinv = rsqrtf(r2);
        const float r    = r2 * rinv;

        float sw;
        if (r < 2.f)      sw = 1.f;
        else if (r < 6.f) sw = fmaf(0.5f, cospif((r - 2.f) * 0.25f), 0.5f);
        else              sw = 0.f;

        const float s_ij  = (nb < 0) ? 0.f : sw * rinv;
        const float srinv = s_ij * rinv;

        const bool alive = (s_ij != 0.f);
        const unsigned bb = __ballot_sync(FULL, alive);
        if (alive) {
            // pack type-pair into 2 mantissa LSBs of s_ij (|ds/s| <= 2^-22)
            const unsigned se = (__float_as_uint(s_ij) & ~3u)
                              | (unsigned)(ti2 + (int)pj.w);
            const int pos = cnt + __popc(bb & ((1u << lane) - 1u));
            sh_rt[w][pos] = make_float4(__uint_as_float(se),
                                        dx * srinv, dy * srinv, dz * srinv);
        }
        cnt += __popc(bb);
    }
    // 4 zero-pad slots: s=0 -> rt=0 -> contribution exactly 0 (row clamps to 0)
    if (lane < 4)
        sh_rt[w][cnt + lane] = make_float4(0.f, 0.f, 0.f, 0.f);
    __syncwarp();

    unsigned long long A01 = 0ull, A23 = 0ull;   // (A0,A1),(A2,A3)

    // -------- Phase 2: blind 4-wide table-lookup pipeline --------
    if (cnt > 0) {
        float  ss[4];
        float2 si[4];
        #pragma unroll
        for (int j = 0; j < 4; j++) {
            const float s = sh_rt[w][j].x;
            ss[j] = s;
            const unsigned u = __float_as_uint(s);
            const int ttj = (int)(u & 3u);
            int c = (int)(u >> CSHIFT) - EBASE;
            c = max(min(c, CELLS - 1), 0);
            si[j] = __ldg(&g_tab[(ttj * CELLS + c) * 32 + lane]);
        }

        for (int i = 0; i < cnt; i += 4) {
            const bool more = (i + 4 < cnt);   // warp-uniform
            float  ns[4];
            float2 nsi[4];
            if (more) {
                #pragma unroll
                for (int j = 0; j < 4; j++) {
                    const float s = sh_rt[w][i + 4 + j].x;
                    ns[j] = s;
                    const unsigned u = __float_as_uint(s);
                    const int ttj = (int)(u & 3u);
                    int c = (int)(u >> CSHIFT) - EBASE;
                    c = max(min(c, CELLS - 1), 0);
                    nsi[j] = __ldg(&g_tab[(ttj * CELLS + c) * 32 + lane]);
                }
            }

            #pragma unroll
            for (int j = 0; j < 4; j++) {
                const float G = fmaf(si[j].x, ss[j], si[j].y);
                const unsigned long long G2 = pack2(G, G);
                const ulonglong2 rt2 =
                    *reinterpret_cast<const ulonglong2*>(&sh_rt[w][i + j]);
                ffma2(A01, G2, rt2.x);
                ffma2(A23, G2, rt2.y);
            }
            if (more) {
                #pragma unroll
                for (int j = 0; j < 4; j++) { ss[j] = ns[j]; si[j] = nsi[j]; }
            }
        }
    }

    // -------- Epilogue: D[g][k] = sum_d A[g][d]*A[k][d], k < 16 ------------
    float a0, a1, a2, a3;
    unpack2(A01, a0, a1);
    unpack2(A23, a2, a3);

    float* shT = reinterpret_cast<float*>(&sh_rt[w][0]);
    __syncwarp();
    shT[0 * 32 + lane] = a0;
    shT[1 * 32 + lane] = a1;
    shT[2 * 32 + lane] = a2;
    shT[3 * 32 + lane] = a3;
    __syncwarp();

    const unsigned long long d0 = pack2(a0, a0);
    const unsigned long long d1 = pack2(a1, a1);
    const unsigned long long d2 = pack2(a2, a2);
    const unsigned long long d3 = pack2(a3, a3);

    float4* o4 = reinterpret_cast<float4*>(out + (size_t)atom * 512 + lane * 16);
    #pragma unroll
    for (int kg = 0; kg < 4; kg++) {
        const int k0 = kg * 4;
        const ulonglong2 r0 = *reinterpret_cast<const ulonglong2*>(&shT[0 * 32 + k0]);
        const ulonglong2 r1 = *reinterpret_cast<const ulonglong2*>(&shT[1 * 32 + k0]);
        const ulonglong2 r2 = *reinterpret_cast<const ulonglong2*>(&shT[2 * 32 + k0]);
        const ulonglong2 r3 = *reinterpret_cast<const ulonglong2*>(&shT[3 * 32 + k0]);

        unsigned long long accA = mul2(d0, r0.x);   // (d[k0], d[k0+1])
        unsigned long long accB = mul2(d0, r0.y);   // (d[k0+2], d[k0+3])
        ffma2(accA, d1, r1.x);  ffma2(accB, d1, r1.y);
        ffma2(accA, d2, r2.x);  ffma2(accB, d2, r2.y);
        ffma2(accA, d3, r3.x);  ffma2(accB, d3, r3.y);

        float4 res;
        unpack2(accA, res.x, res.y);
        unpack2(accB, res.z, res.w);
        o4[kg] = res;
    }
}

// ---------------------------------------------------------------------------
extern "C" void kernel_launch(void* const* d_in, const int* in_sizes, int n_in,
                              void* d_out, int out_size)
{
    const float* inputs      = (const float*)d_in[0];
    const int*   input_types = (const int*)  d_in[1];
    const int*   neigh_list  = (const int*)  d_in[2];
    const float* es1_w = (const float*)d_in[3];
    const float* es1_b = (const float*)d_in[4];
    const float* es2_w = (const float*)d_in[5];
    const float* es2_b = (const float*)d_in[6];
    const float* fs1_w = (const float*)d_in[7];
    const float* fs1_b = (const float*)d_in[8];
    const float* fs2_w = (const float*)d_in[9];
    const float* fs2_b = (const float*)d_in[10];
    const float* en1_w = (const float*)d_in[11];
    const float* en1_b = (const float*)d_in[12];
    const float* en2_w = (const float*)d_in[13];
    const float* en2_b = (const float*)d_in[14];
    const float* en3_w = (const float*)d_in[15];
    const float* en3_b = (const float*)d_in[16];
    float* out = (float*)d_out;

    prep_kernel<<<PACK_BLOCKS + TAB_BLOCKS, 256>>>(
        inputs, input_types,
        es1_w, es1_b, es2_w, es2_b,
        fs1_w, fs1_b, fs2_w, fs2_b,
        en1_w, en1_b, en2_w, en2_b, en3_w, en3_b);

    descriptor_kernel<<<SN / 8, 256>>>(neigh_list, out);
}

// round 16
// speedup vs baseline: 1.4369x; 1.2051x over previous
#include <cuda_runtime.h>
#include <cstdint>

#define FULL 0xffffffffu

static constexpr int S = 8;
static constexpr int N = 4096;
static constexpr int M = 64;
static constexpr int SN = S * N;

static constexpr int CPO   = 32;                  // cells per octave
static constexpr int CELLS = 17 * CPO;            // 544
static constexpr int EBASE = (127 - 12) * CPO;    // s_min = 2^-12
static constexpr int CSHIFT = 18;                 // 23 - log2(CPO)
static constexpr int PACK_BLOCKS = SN / 4 / 256;  // 32
static constexpr int CPW = 7;                     // cells per warp (short sweep)
static constexpr int WARPS_PER_TT = (CELLS + CPW - 1) / CPW;   // 78
static constexpr int TAB_WARPS = 4 * WARPS_PER_TT;             // 312
static constexpr int TAB_BLOCKS = (TAB_WARPS + 7) / 8;         // 39

__device__ float4 g_pos4[SN];             // (x, y, z, type)
__device__ float2 g_tab[4 * CELLS * 32];  // (slope, intercept)[tt][cell][g]

// ---------------- packed f32x2 helpers (sm_103a FFMA2) ----------------
__device__ __forceinline__ void ffma2(unsigned long long& d,
                                      unsigned long long a,
                                      unsigned long long b) {
    asm("fma.rn.f32x2 %0, %1, %2, %0;" : "+l"(d) : "l"(a), "l"(b));
}
__device__ __forceinline__ unsigned long long mul2(unsigned long long a,
                                                   unsigned long long b) {
    unsigned long long d;
    asm("mul.rn.f32x2 %0, %1, %2;" : "=l"(d) : "l"(a), "l"(b));
    return d;
}
__device__ __forceinline__ unsigned long long pack2(float lo, float hi) {
    unsigned long long d;
    asm("mov.b64 %0, {%1, %2};" : "=l"(d) : "f"(lo), "f"(hi));
    return d;
}
__device__ __forceinline__ void unpack2(unsigned long long v,
                                        float& lo, float& hi) {
    asm("mov.b64 {%0, %1}, %2;" : "=f"(lo), "=f"(hi) : "l"(v));
}

// ---------------------------------------------------------------------------
// Prep kernel.
//  blocks [0, PACK_BLOCKS): pack positions+type into float4 (vectorized)
//  blocks [PACK_BLOCKS, +TAB_BLOCKS): PWL table build, short 7-cell sweeps.
// ---------------------------------------------------------------------------
__global__ void prep_kernel(
    const float* __restrict__ pos, const int* __restrict__ types,
    const float* __restrict__ es1_w, const float* __restrict__ es1_b,
    const float* __restrict__ es2_w, const float* __restrict__ es2_b,
    const float* __restrict__ fs1_w, const float* __restrict__ fs1_b,
    const float* __restrict__ fs2_w, const float* __restrict__ fs2_b,
    const float* __restrict__ en1_w, const float* __restrict__ en1_b,
    const float* __restrict__ en2_w, const float* __restrict__ en2_b,
    const float* __restrict__ en3_w, const float* __restrict__ en3_b)
{
    if (blockIdx.x < PACK_BLOCKS) {
        const int idx = blockIdx.x * blockDim.x + threadIdx.x;
        const float4* pv = reinterpret_cast<const float4*>(pos) + idx * 3;
        const float4 a = pv[0], b = pv[1], c = pv[2];
        const int4 t = reinterpret_cast<const int4*>(types)[idx];
        float4* o = g_pos4 + idx * 4;
        o[0] = make_float4(a.x, a.y, a.z, (float)t.x);
        o[1] = make_float4(a.w, b.x, b.y, (float)t.y);
        o[2] = make_float4(b.z, b.w, c.x, (float)t.z);
        o[3] = make_float4(c.y, c.z, c.w, (float)t.w);
        return;
    }

    __shared__ float s_es1w[8],  s_es1b[4],  s_es2w[16], s_es2b[4];
    __shared__ float s_fs1w[16], s_fs1b[4],  s_fs2w[16], s_fs2b[4];
    __shared__ float s_en1w[32], s_en1b[8],  s_en2w[128], s_en2b[16];
    __shared__ float s_en3w[512], s_en3b[32];
    __shared__ float s_h2[8][8][16];

    const int t = threadIdx.x;
    // ---- one parallel load round: disjoint thread ranges ----
    if      (t < 8)   s_es1w[t]       = es1_w[t];
    else if (t < 12)  s_es1b[t - 8]   = es1_b[t - 8];
    else if (t < 28)  s_es2w[t - 12]  = es2_w[t - 12];
    else if (t < 32)  s_es2b[t - 28]  = es2_b[t - 28];
    else if (t < 48)  s_fs1w[t - 32]  = fs1_w[t - 32];
    else if (t < 52)  s_fs1b[t - 48]  = fs1_b[t - 48];
    else if (t < 68)  s_fs2w[t - 52]  = fs2_w[t - 52];
    else if (t < 72)  s_fs2b[t - 68]  = fs2_b[t - 68];
    else if (t < 104) s_en1w[t - 72]  = en1_w[t - 72];
    else if (t < 112) s_en1b[t - 104] = en1_b[t - 104];
    else if (t < 128) s_en2b[t - 112] = en2_b[t - 112];
    else              s_en2w[t - 128] = en2_w[t - 128];
    s_en3w[t]       = en3_w[t];
    s_en3w[t + 256] = en3_w[t + 256];
    if (t >= 192 && t < 224) s_en3b[t - 192] = en3_b[t - 192];
    __syncthreads();

    const int lane = t & 31;
    const int w    = t >> 5;
    const int gwid = (blockIdx.x - PACK_BLOCKS) * 8 + w;
    if (gwid >= TAB_WARPS) return;
    const int tt = gwid / WARPS_PER_TT;
    const int wb = gwid % WARPS_PER_TT;

    // ---- every lane recomputes td/v8 from shared (pure ALU) ----
    float v8[8];
    {
        const float ti = (float)(tt >> 1);
        const float tj = (float)(tt & 1);
        float e4[4] = {0.f, 0.f, 0.f, 0.f};
        #pragma unroll
        for (int pass = 0; pass < 2; pass++) {
            const float a0 = pass ? tj : ti;
            const float a1 = pass ? ti : tj;
            float h[4];
            #pragma unroll
            for (int k = 0; k < 4; k++)
                h[k] = fmaxf(a0 * s_es1w[k] + a1 * s_es1w[4 + k] + s_es1b[k], 0.f);
            #pragma unroll
            for (int k = 0; k < 4; k++) {
                float aa = s_es2b[k];
                #pragma unroll
                for (int j = 0; j < 4; j++) aa += h[j] * s_es2w[j * 4 + k];
                e4[k] += aa;
            }
        }
        float y4[4];
        #pragma unroll
        for (int k = 0; k < 4; k++) {
            float aa = s_fs1b[k];
            #pragma unroll
            for (int j = 0; j < 4; j++) aa += e4[j] * s_fs1w[j * 4 + k];
            y4[k] = fmaxf(aa, 0.f);
        }
        float td[4];
        #pragma unroll
        for (int k = 0; k < 4; k++) {
            float aa = s_fs2b[k];
            #pragma unroll
            for (int j = 0; j < 4; j++) aa += y4[j] * s_fs2w[j * 4 + k];
            td[k] = aa;
        }
        #pragma unroll
        for (int o = 0; o < 8; o++) {
            float aa = 0.f;
            #pragma unroll
            for (int d = 0; d < 4; d++) aa += td[d] * s_en1w[d * 8 + o];
            v8[o] = aa;
        }
    }

    // ---- lanes 0-7 compute h2[16] at their endpoint ----
    if (lane < 8) {
        const int e_id = min(wb * CPW + lane, CELLS);
        const float se = __uint_as_float((unsigned)(EBASE + e_id) << CSHIFT);
        float h1[8];
        #pragma unroll
        for (int o = 0; o < 8; o++)
            h1[o] = fmaxf(fmaf(se, v8[o], s_en1b[o]), 0.f);
        #pragma unroll
        for (int c = 0; c < 16; c++) {
            float aa = s_en2b[c];
            #pragma unroll
            for (int j = 0; j < 8; j++)
                aa = fmaf(h1[j], s_en2w[j * 16 + c], aa);
            s_h2[w][lane][c] = fmaxf(aa, 0.f);
        }
    }
    __syncwarp();

    // ---- lane g sweeps 8 endpoints, emits slope/intercept per cell ----
    const int g = lane;
    float2 W3f[8];
    #pragma unroll
    for (int q = 0; q < 8; q++) {
        W3f[q].x = s_en3w[(2 * q)     * 32 + g];
        W3f[q].y = s_en3w[(2 * q + 1) * 32 + g];
    }
    const unsigned long long b3g2 = pack2(s_en3b[g], 0.f);

    float Gp = 0.f, sp = 0.f;
    #pragma unroll
    for (int e2 = 0; e2 < 8; e2++) {
        const ulonglong2* hq = reinterpret_cast<const ulonglong2*>(s_h2[w][e2]);
        const ulonglong2 hA = hq[0];
        const ulonglong2 hB = hq[1];
        unsigned long long acc = b3g2;
        ffma2(acc, hA.x, *reinterpret_cast<const unsigned long long*>(&W3f[0]));
        ffma2(acc, hA.y, *reinterpret_cast<const unsigned long long*>(&W3f[1]));
        ffma2(acc, hB.x, *reinterpret_cast<const unsigned long long*>(&W3f[2]));
        ffma2(acc, hB.y, *reinterpret_cast<const unsigned long long*>(&W3f[3]));
        const ulonglong2 hC = hq[2];
        const ulonglong2 hD = hq[3];
        ffma2(acc, hC.x, *reinterpret_cast<const unsigned long long*>(&W3f[4]));
        ffma2(acc, hC.y, *reinterpret_cast<const unsigned long long*>(&W3f[5]));
        ffma2(acc, hD.x, *reinterpret_cast<const unsigned long long*>(&W3f[6]));
        ffma2(acc, hD.y, *reinterpret_cast<const unsigned long long*>(&W3f[7]));
        float glo, ghi;
        unpack2(acc, glo, ghi);
        const float Gc = glo + ghi;
        const float sc = __uint_as_float(
            (unsigned)(EBASE + min(wb * CPW + e2, CELLS)) << CSHIFT);

        const int cell = wb * CPW + e2 - 1;
        if (e2 > 0 && cell < CELLS) {
            const float slope = (Gc - Gp) / (sc - sp);
            g_tab[(tt * CELLS + cell) * 32 + g] =
                make_float2(slope, fmaf(-slope, sp, Gp));
        }
        Gp = Gc; sp = sc;
    }
}

// ---------------------------------------------------------------------------
// Main kernel: one warp per atom; compacted survivors, tt in s mantissa LSBs;
// blind 4-wide G lookup + FFMA2; epilogue remapped so every STG.128 is
// fully coalesced (lane -> contiguous 16B of the atom's 2KB output).
// ---------------------------------------------------------------------------
__global__ __launch_bounds__(256, 4)
void descriptor_kernel(
    const int* __restrict__ neigh,   // [S,N,M]
    float*     __restrict__ out)     // [S,N,32,16]
{
    __shared__ float4 sh_rt[8][68];

    const int tid  = threadIdx.x;
    const int lane = tid & 31;
    const int w    = tid >> 5;

    const int atom = blockIdx.x * 8 + w;      // atom = s*N + n
    const int base = atom & ~4095;            // snapshot base (N = 4096)

    const float4 pi = g_pos4[atom];
    const int    ti2 = 2 * (int)pi.w;

    // -------- Phase 1: prefetch gathers, then geometry + compaction --------
    const int2 nb2 = reinterpret_cast<const int2*>(neigh + atom * M)[lane];
    const int jj0 = (nb2.x < 0) ? 0 : nb2.x;
    const int jj1 = (nb2.y < 0) ? 0 : nb2.y;
    const float4 pj0 = g_pos4[base + jj0];
    const float4 pj1 = g_pos4[base + jj1];

    int cnt = 0;
    #pragma unroll
    for (int p = 0; p < 2; p++) {
        const int    nb = (p == 0) ? nb2.x : nb2.y;
        const float4 pj = (p == 0) ? pj0 : pj1;

        float dx = pj.x - pi.x; dx -= 20.f * rintf(dx * 0.05f);
        float dy = pj.y - pi.y; dy -= 20.f * rintf(dy * 0.05f);
        float dz = pj.z - pi.z; dz -= 20.f * rintf(dz * 0.05f);

        const float r2   = fmaf(dx, dx, fmaf(dy, dy, fmaf(dz, dz, 1e-12f)));
        const float rinv = rsqrtf(r2);
        const float r    = r2 * rinv;

        float sw;
        if (r < 2.f)      sw = 1.f;
        else if (r < 6.f) sw = fmaf(0.5f, cospif((r - 2.f) * 0.25f), 0.5f);
        else              sw = 0.f;

        const float s_ij  = (nb < 0) ? 0.f : sw * rinv;
        const float srinv = s_ij * rinv;

        const bool alive = (s_ij != 0.f);
        const unsigned bb = __ballot_sync(FULL, alive);
        if (alive) {
            // pack type-pair into 2 mantissa LSBs of s_ij (|ds/s| <= 2^-22)
            const unsigned se = (__float_as_uint(s_ij) & ~3u)
                              | (unsigned)(ti2 + (int)pj.w);
            const int pos = cnt + __popc(bb & ((1u << lane) - 1u));
            sh_rt[w][pos] = make_float4(__uint_as_float(se),
                                        dx * srinv, dy * srinv, dz * srinv);
        }
        cnt += __popc(bb);
    }
    // 4 zero-pad slots: s=0 -> rt=0 -> contribution exactly 0 (row clamps to 0)
    if (lane < 4)
        sh_rt[w][cnt + lane] = make_float4(0.f, 0.f, 0.f, 0.f);
    __syncwarp();

    unsigned long long A01 = 0ull, A23 = 0ull;   // (A0,A1),(A2,A3)

    // -------- Phase 2: blind 4-wide table-lookup pipeline --------
    if (cnt > 0) {
        float  ss[4];
        float2 si[4];
        #pragma unroll
        for (int j = 0; j < 4; j++) {
            const float s = sh_rt[w][j].x;
            ss[j] = s;
            const unsigned u = __float_as_uint(s);
            const int ttj = (int)(u & 3u);
            int c = (int)(u >> CSHIFT) - EBASE;
            c = max(min(c, CELLS - 1), 0);
            si[j] = __ldg(&g_tab[(ttj * CELLS + c) * 32 + lane]);
        }

        for (int i = 0; i < cnt; i += 4) {
            const bool more = (i + 4 < cnt);   // warp-uniform
            float  ns[4];
            float2 nsi[4];
            if (more) {
                #pragma unroll
                for (int j = 0; j < 4; j++) {
                    const float s = sh_rt[w][i + 4 + j].x;
                    ns[j] = s;
                    const unsigned u = __float_as_uint(s);
                    const int ttj = (int)(u & 3u);
                    int c = (int)(u >> CSHIFT) - EBASE;
                    c = max(min(c, CELLS - 1), 0);
                    nsi[j] = __ldg(&g_tab[(ttj * CELLS + c) * 32 + lane]);
                }
            }

            #pragma unroll
            for (int j = 0; j < 4; j++) {
                const float G = fmaf(si[j].x, ss[j], si[j].y);
                const unsigned long long G2 = pack2(G, G);
                const ulonglong2 rt2 =
                    *reinterpret_cast<const ulonglong2*>(&sh_rt[w][i + j]);
                ffma2(A01, G2, rt2.x);
                ffma2(A23, G2, rt2.y);
            }
            if (more) {
                #pragma unroll
                for (int j = 0; j < 4; j++) { ss[j] = ns[j]; si[j] = nsi[j]; }
            }
        }
    }

    // -------- Epilogue: D[g][k] = sum_d A[g][d]*A[k][d], coalesced stores ---
    float a0, a1, a2, a3;
    unpack2(A01, a0, a1);
    unpack2(A23, a2, a3);

    // transposed stash shT[d][k] (reuse sh_rt storage)
    float* shT = reinterpret_cast<float*>(&sh_rt[w][0]);
    __syncwarp();
    shT[0 * 32 + lane] = a0;
    shT[1 * 32 + lane] = a1;
    shT[2 * 32 + lane] = a2;
    shT[3 * 32 + lane] = a3;
    __syncwarp();

    // lane stores output elements i = inst*128 + lane*4 + 0..3
    //   -> g = inst*8 + (lane>>2), k = (lane&3)*4 + 0..3
    const int k0 = (lane & 3) * 4;
    const ulonglong2 r0 = *reinterpret_cast<const ulonglong2*>(&shT[0 * 32 + k0]);
    const ulonglong2 r1 = *reinterpret_cast<const ulonglong2*>(&shT[1 * 32 + k0]);
    const ulonglong2 r2 = *reinterpret_cast<const ulonglong2*>(&shT[2 * 32 + k0]);
    const ulonglong2 r3 = *reinterpret_cast<const ulonglong2*>(&shT[3 * 32 + k0]);

    float* obase = out + (size_t)atom * 512 + lane * 4;
    #pragma unroll
    for (int inst = 0; inst < 4; inst++) {
        const int g = inst * 8 + (lane >> 2);
        const float ag0 = shT[0 * 32 + g];
        const float ag1 = shT[1 * 32 + g];
        const float ag2 = shT[2 * 32 + g];
        const float ag3 = shT[3 * 32 + g];
        const unsigned long long g0 = pack2(ag0, ag0);
        const unsigned long long g1 = pack2(ag1, ag1);
        const unsigned long long g2 = pack2(ag2, ag2);
        const unsigned long long g3 = pack2(ag3, ag3);

        unsigned long long accA = mul2(g0, r0.x);   // (d[k0], d[k0+1])
        unsigned long long accB = mul2(g0, r0.y);   // (d[k0+2], d[k0+3])
        ffma2(accA, g1, r1.x);  ffma2(accB, g1, r1.y);
        ffma2(accA, g2, r2.x);  ffma2(accB, g2, r2.y);
        ffma2(accA, g3, r3.x);  ffma2(accB, g3, r3.y);

        float4 res;
        unpack2(accA, res.x, res.y);
        unpack2(accB, res.z, res.w);
        *reinterpret_cast<float4*>(obase + inst * 128) = res;
    }
}

// ---------------------------------------------------------------------------
extern "C" void kernel_launch(void* const* d_in, const int* in_sizes, int n_in,
                              void* d_out, int out_size)
{
    const float* inputs      = (const float*)d_in[0];
    const int*   input_types = (const int*)  d_in[1];
    const int*   neigh_list  = (const int*)  d_in[2];
    const float* es1_w = (const float*)d_in[3];
    const float* es1_b = (const float*)d_in[4];
    const float* es2_w = (const float*)d_in[5];
    const float* es2_b = (const float*)d_in[6];
    const float* fs1_w = (const float*)d_in[7];
    const float* fs1_b = (const float*)d_in[8];
    const float* fs2_w = (const float*)d_in[9];
    const float* fs2_b = (const float*)d_in[10];
    const float* en1_w = (const float*)d_in[11];
    const float* en1_b = (const float*)d_in[12];
    const float* en2_w = (const float*)d_in[13];
    const float* en2_b = (const float*)d_in[14];
    const float* en3_w = (const float*)d_in[15];
    const float* en3_b = (const float*)d_in[16];
    float* out = (float*)d_out;

    prep_kernel<<<PACK_BLOCKS + TAB_BLOCKS, 256>>>(
        inputs, input_types,
        es1_w, es1_b, es2_w, es2_b,
        fs1_w, fs1_b, fs2_w, fs2_b,
        en1_w, en1_b, en2_w, en2_b, en3_w, en3_b);

    descriptor_kernel<<<SN / 8, 256>>>(neigh_list, out);
}

// round 17
// speedup vs baseline: 1.4458x; 1.0062x over previous
#include <cuda_runtime.h>
#include <cstdint>

#define FULL 0xffffffffu

static constexpr int S = 8;
static constexpr int N = 4096;
static constexpr int M = 64;
static constexpr int SN = S * N;

static constexpr int CPO   = 32;                  // cells per octave
static constexpr int CELLS = 17 * CPO;            // 544
static constexpr int EBASE = (127 - 12) * CPO;    // s_min = 2^-12
static constexpr int CSHIFT = 18;                 // 23 - log2(CPO)
static constexpr int PACK_BLOCKS = SN / 2 / 256;  // 64  (2 atoms per thread)
static constexpr int CPW = 7;                     // cells per warp (short sweep)
static constexpr int WARPS_PER_TT = (CELLS + CPW - 1) / CPW;   // 78
static constexpr int TAB_WARPS = 4 * WARPS_PER_TT;             // 312
static constexpr int TAB_BLOCKS = (TAB_WARPS + 7) / 8;         // 39

__device__ float4 g_pos4[SN];             // (x, y, z, type)
__device__ float2 g_tab[4 * CELLS * 32];  // (slope, intercept)[tt][cell][g]

// ---------------- packed f32x2 helpers (sm_103a FFMA2) ----------------
__device__ __forceinline__ void ffma2(unsigned long long& d,
                                      unsigned long long a,
                                      unsigned long long b) {
    asm("fma.rn.f32x2 %0, %1, %2, %0;" : "+l"(d) : "l"(a), "l"(b));
}
__device__ __forceinline__ unsigned long long mul2(unsigned long long a,
                                                   unsigned long long b) {
    unsigned long long d;
    asm("mul.rn.f32x2 %0, %1, %2;" : "=l"(d) : "l"(a), "l"(b));
    return d;
}
__device__ __forceinline__ unsigned long long pack2(float lo, float hi) {
    unsigned long long d;
    asm("mov.b64 %0, {%1, %2};" : "=l"(d) : "f"(lo), "f"(hi));
    return d;
}
__device__ __forceinline__ void unpack2(unsigned long long v,
                                        float& lo, float& hi) {
    asm("mov.b64 {%0, %1}, %2;" : "=f"(lo), "=f"(hi) : "l"(v));
}

// ---------------------------------------------------------------------------
// Prep kernel (256 threads/block).
//  blocks [0, PACK_BLOCKS): pack positions+type, 2 atoms per thread.
//  blocks [PACK_BLOCKS, +TAB_BLOCKS): PWL table build, short 7-cell sweeps.
// ---------------------------------------------------------------------------
__global__ void prep_kernel(
    const float* __restrict__ pos, const int* __restrict__ types,
    const float* __restrict__ es1_w, const float* __restrict__ es1_b,
    const float* __restrict__ es2_w, const float* __restrict__ es2_b,
    const float* __restrict__ fs1_w, const float* __restrict__ fs1_b,
    const float* __restrict__ fs2_w, const float* __restrict__ fs2_b,
    const float* __restrict__ en1_w, const float* __restrict__ en1_b,
    const float* __restrict__ en2_w, const float* __restrict__ en2_b,
    const float* __restrict__ en3_w, const float* __restrict__ en3_b)
{
    if (blockIdx.x < PACK_BLOCKS) {
        const int idx = blockIdx.x * blockDim.x + threadIdx.x;  // atom pair
        const float2* pv = reinterpret_cast<const float2*>(pos) + idx * 3;
        const float2 a = pv[0], b = pv[1], c = pv[2];
        const int2 t = reinterpret_cast<const int2*>(types)[idx];
        float4* o = g_pos4 + idx * 2;
        o[0] = make_float4(a.x, a.y, b.x, (float)t.x);
        o[1] = make_float4(b.y, c.x, c.y, (float)t.y);
        return;
    }

    __shared__ float s_es1w[8],  s_es1b[4],  s_es2w[16], s_es2b[4];
    __shared__ float s_fs1w[16], s_fs1b[4],  s_fs2w[16], s_fs2b[4];
    __shared__ float s_en1w[32], s_en1b[8],  s_en2w[128], s_en2b[16];
    __shared__ float s_en3w[512], s_en3b[32];
    __shared__ float s_h2[8][8][16];

    const int t = threadIdx.x;
    // ---- one parallel load round: disjoint thread ranges ----
    if      (t < 8)   s_es1w[t]       = es1_w[t];
    else if (t < 12)  s_es1b[t - 8]   = es1_b[t - 8];
    else if (t < 28)  s_es2w[t - 12]  = es2_w[t - 12];
    else if (t < 32)  s_es2b[t - 28]  = es2_b[t - 28];
    else if (t < 48)  s_fs1w[t - 32]  = fs1_w[t - 32];
    else if (t < 52)  s_fs1b[t - 48]  = fs1_b[t - 48];
    else if (t < 68)  s_fs2w[t - 52]  = fs2_w[t - 52];
    else if (t < 72)  s_fs2b[t - 68]  = fs2_b[t - 68];
    else if (t < 104) s_en1w[t - 72]  = en1_w[t - 72];
    else if (t < 112) s_en1b[t - 104] = en1_b[t - 104];
    else if (t < 128) s_en2b[t - 112] = en2_b[t - 112];
    else              s_en2w[t - 128] = en2_w[t - 128];
    s_en3w[t]       = en3_w[t];
    s_en3w[t + 256] = en3_w[t + 256];
    if (t >= 192 && t < 224) s_en3b[t - 192] = en3_b[t - 192];
    __syncthreads();

    const int lane = t & 31;
    const int w    = t >> 5;
    const int gwid = (blockIdx.x - PACK_BLOCKS) * 8 + w;
    if (gwid >= TAB_WARPS) return;
    const int tt = gwid / WARPS_PER_TT;
    const int wb = gwid % WARPS_PER_TT;

    // ---- every lane recomputes td/v8 from shared (pure ALU) ----
    float v8[8];
    {
        const float ti = (float)(tt >> 1);
        const float tj = (float)(tt & 1);
        float e4[4] = {0.f, 0.f, 0.f, 0.f};
        #pragma unroll
        for (int pass = 0; pass < 2; pass++) {
            const float a0 = pass ? tj : ti;
            const float a1 = pass ? ti : tj;
            float h[4];
            #pragma unroll
            for (int k = 0; k < 4; k++)
                h[k] = fmaxf(a0 * s_es1w[k] + a1 * s_es1w[4 + k] + s_es1b[k], 0.f);
            #pragma unroll
            for (int k = 0; k < 4; k++) {
                float aa = s_es2b[k];
                #pragma unroll
                for (int j = 0; j < 4; j++) aa += h[j] * s_es2w[j * 4 + k];
                e4[k] += aa;
            }
        }
        float y4[4];
        #pragma unroll
        for (int k = 0; k < 4; k++) {
            float aa = s_fs1b[k];
            #pragma unroll
            for (int j = 0; j < 4; j++) aa += e4[j] * s_fs1w[j * 4 + k];
            y4[k] = fmaxf(aa, 0.f);
        }
        float td[4];
        #pragma unroll
        for (int k = 0; k < 4; k++) {
            float aa = s_fs2b[k];
            #pragma unroll
            for (int j = 0; j < 4; j++) aa += y4[j] * s_fs2w[j * 4 + k];
            td[k] = aa;
        }
        #pragma unroll
        for (int o = 0; o < 8; o++) {
            float aa = 0.f;
            #pragma unroll
            for (int d = 0; d < 4; d++) aa += td[d] * s_en1w[d * 8 + o];
            v8[o] = aa;
        }
    }

    // ---- lanes 0-7 compute h2[16] at their endpoint ----
    if (lane < 8) {
        const int e_id = min(wb * CPW + lane, CELLS);
        const float se = __uint_as_float((unsigned)(EBASE + e_id) << CSHIFT);
        float h1[8];
        #pragma unroll
        for (int o = 0; o < 8; o++)
            h1[o] = fmaxf(fmaf(se, v8[o], s_en1b[o]), 0.f);
        #pragma unroll
        for (int c = 0; c < 16; c++) {
            float aa = s_en2b[c];
            #pragma unroll
            for (int j = 0; j < 8; j++)
                aa = fmaf(h1[j], s_en2w[j * 16 + c], aa);
            s_h2[w][lane][c] = fmaxf(aa, 0.f);
        }
    }
    __syncwarp();

    // ---- lane g sweeps 8 endpoints, emits slope/intercept per cell ----
    const int g = lane;
    float2 W3f[8];
    #pragma unroll
    for (int q = 0; q < 8; q++) {
        W3f[q].x = s_en3w[(2 * q)     * 32 + g];
        W3f[q].y = s_en3w[(2 * q + 1) * 32 + g];
    }
    const unsigned long long b3g2 = pack2(s_en3b[g], 0.f);

    float Gp = 0.f, sp = 0.f;
    #pragma unroll
    for (int e2 = 0; e2 < 8; e2++) {
        const ulonglong2* hq = reinterpret_cast<const ulonglong2*>(s_h2[w][e2]);
        const ulonglong2 hA = hq[0];
        const ulonglong2 hB = hq[1];
        unsigned long long acc = b3g2;
        ffma2(acc, hA.x, *reinterpret_cast<const unsigned long long*>(&W3f[0]));
        ffma2(acc, hA.y, *reinterpret_cast<const unsigned long long*>(&W3f[1]));
        ffma2(acc, hB.x, *reinterpret_cast<const unsigned long long*>(&W3f[2]));
        ffma2(acc, hB.y, *reinterpret_cast<const unsigned long long*>(&W3f[3]));
        const ulonglong2 hC = hq[2];
        const ulonglong2 hD = hq[3];
        ffma2(acc, hC.x, *reinterpret_cast<const unsigned long long*>(&W3f[4]));
        ffma2(acc, hC.y, *reinterpret_cast<const unsigned long long*>(&W3f[5]));
        ffma2(acc, hD.x, *reinterpret_cast<const unsigned long long*>(&W3f[6]));
        ffma2(acc, hD.y, *reinterpret_cast<const unsigned long long*>(&W3f[7]));
        float glo, ghi;
        unpack2(acc, glo, ghi);
        const float Gc = glo + ghi;
        const float sc = __uint_as_float(
            (unsigned)(EBASE + min(wb * CPW + e2, CELLS)) << CSHIFT);

        const int cell = wb * CPW + e2 - 1;
        if (e2 > 0 && cell < CELLS) {
            const float slope = (Gc - Gp) / (sc - sp);
            g_tab[(tt * CELLS + cell) * 32 + g] =
                make_float2(slope, fmaf(-slope, sp, Gp));
        }
        Gp = Gc; sp = sc;
    }
}

// ---------------------------------------------------------------------------
// Main kernel: 128-thread blocks (finer tail granularity), one warp per atom;
// compacted survivors, tt in s mantissa LSBs; blind 4-wide G lookup + FFMA2;
// fully coalesced epilogue stores.
// ---------------------------------------------------------------------------
__global__ __launch_bounds__(128, 8)
void descriptor_kernel(
    const int* __restrict__ neigh,   // [S,N,M]
    float*     __restrict__ out)     // [S,N,32,16]
{
    __shared__ float4 sh_rt[4][68];

    const int tid  = threadIdx.x;
    const int lane = tid & 31;
    const int w    = tid >> 5;

    const int atom = blockIdx.x * 4 + w;      // atom = s*N + n
    const int base = atom & ~4095;            // snapshot base (N = 4096)

    const float4 pi = g_pos4[atom];
    const int    ti2 = 2 * (int)pi.w;

    // -------- Phase 1: prefetch gathers, then geometry + compaction --------
    const int2 nb2 = reinterpret_cast<const int2*>(neigh + atom * M)[lane];
    const int jj0 = (nb2.x < 0) ? 0 : nb2.x;
    const int jj1 = (nb2.y < 0) ? 0 : nb2.y;
    const float4 pj0 = g_pos4[base + jj0];
    const float4 pj1 = g_pos4[base + jj1];

    int cnt = 0;
    #pragma unroll
    for (int p = 0; p < 2; p++) {
        const int    nb = (p == 0) ? nb2.x : nb2.y;
        const float4 pj = (p == 0) ? pj0 : pj1;

        float dx = pj.x - pi.x; dx -= 20.f * rintf(dx * 0.05f);
        float dy = pj.y - pi.y; dy -= 20.f * rintf(dy * 0.05f);
        float dz = pj.z - pi.z; dz -= 20.f * rintf(dz * 0.05f);

        const float r2   = fmaf(dx, dx, fmaf(dy, dy, fmaf(dz, dz, 1e-12f)));
        const float rinv = rsqrtf(r2);
        const float r    = r2 * rinv;

        float sw;
        if (r < 2.f)      sw = 1.f;
        else if (r < 6.f) sw = fmaf(0.5f, cospif((r - 2.f) * 0.25f), 0.5f);
        else              sw = 0.f;

        const float s_ij  = (nb < 0) ? 0.f : sw * rinv;
        const float srinv = s_ij * rinv;

        const bool alive = (s_ij != 0.f);
        const unsigned bb = __ballot_sync(FULL, alive);
        if (alive) {
            // pack type-pair into 2 mantissa LSBs of s_ij (|ds/s| <= 2^-22)
            const unsigned se = (__float_as_uint(s_ij) & ~3u)
                              | (unsigned)(ti2 + (int)pj.w);
            const int pos = cnt + __popc(bb & ((1u << lane) - 1u));
            sh_rt[w][pos] = make_float4(__uint_as_float(se),
                                        dx * srinv, dy * srinv, dz * srinv);
        }
        cnt += __popc(bb);
    }
    // 4 zero-pad slots: s=0 -> rt=0 -> contribution exactly 0 (row clamps to 0)
    if (lane < 4)
        sh_rt[w][cnt + lane] = make_float4(0.f, 0.f, 0.f, 0.f);
    __syncwarp();

    unsigned long long A01 = 0ull, A23 = 0ull;   // (A0,A1),(A2,A3)

    // -------- Phase 2: blind 4-wide table-lookup pipeline --------
    if (cnt > 0) {
        float  ss[4];
        float2 si[4];
        #pragma unroll
        for (int j = 0; j < 4; j++) {
            const float s = sh_rt[w][j].x;
            ss[j] = s;
            const unsigned u = __float_as_uint(s);
            const int ttj = (int)(u & 3u);
            int c = (int)(u >> CSHIFT) - EBASE;
            c = max(min(c, CELLS - 1), 0);
            si[j] = __ldg(&g_tab[(ttj * CELLS + c) * 32 + lane]);
        }

        for (int i = 0; i < cnt; i += 4) {
            const bool more = (i + 4 < cnt);   // warp-uniform
            float  ns[4];
            float2 nsi[4];
            if (more) {
                #pragma unroll
                for (int j = 0; j < 4; j++) {
                    const float s = sh_rt[w][i + 4 + j].x;
                    ns[j] = s;
                    const unsigned u = __float_as_uint(s);
                    const int ttj = (int)(u & 3u);
                    int c = (int)(u >> CSHIFT) - EBASE;
                    c = max(min(c, CELLS - 1), 0);
                    nsi[j] = __ldg(&g_tab[(ttj * CELLS + c) * 32 + lane]);
                }
            }

            #pragma unroll
            for (int j = 0; j < 4; j++) {
                const float G = fmaf(si[j].x, ss[j], si[j].y);
                const unsigned long long G2 = pack2(G, G);
                const ulonglong2 rt2 =
                    *reinterpret_cast<const ulonglong2*>(&sh_rt[w][i + j]);
                ffma2(A01, G2, rt2.x);
                ffma2(A23, G2, rt2.y);
            }
            if (more) {
                #pragma unroll
                for (int j = 0; j < 4; j++) { ss[j] = ns[j]; si[j] = nsi[j]; }
            }
        }
    }

    // -------- Epilogue: D[g][k] = sum_d A[g][d]*A[k][d], coalesced stores ---
    float a0, a1, a2, a3;
    unpack2(A01, a0, a1);
    unpack2(A23, a2, a3);

    // transposed stash shT[d][k] (reuse sh_rt storage)
    float* shT = reinterpret_cast<float*>(&sh_rt[w][0]);
    __syncwarp();
    shT[0 * 32 + lane] = a0;
    shT[1 * 32 + lane] = a1;
    shT[2 * 32 + lane] = a2;
    shT[3 * 32 + lane] = a3;
    __syncwarp();

    // lane stores output elements i = inst*128 + lane*4 + 0..3
    //   -> g = inst*8 + (lane>>2), k = (lane&3)*4 + 0..3
    const int k0 = (lane & 3) * 4;
    const ulonglong2 r0 = *reinterpret_cast<const ulonglong2*>(&shT[0 * 32 + k0]);
    const ulonglong2 r1 = *reinterpret_cast<const ulonglong2*>(&shT[1 * 32 + k0]);
    const ulonglong2 r2 = *reinterpret_cast<const ulonglong2*>(&shT[2 * 32 + k0]);
    const ulonglong2 r3 = *reinterpret_cast<const ulonglong2*>(&shT[3 * 32 + k0]);

    float* obase = out + (size_t)atom * 512 + lane * 4;
    #pragma unroll
    for (int inst = 0; inst < 4; inst++) {
        const int g = inst * 8 + (lane >> 2);
        const float ag0 = shT[0 * 32 + g];
        const float ag1 = shT[1 * 32 + g];
        const float ag2 = shT[2 * 32 + g];
        const float ag3 = shT[3 * 32 + g];
        const unsigned long long g0 = pack2(ag0, ag0);
        const unsigned long long g1 = pack2(ag1, ag1);
        const unsigned long long g2 = pack2(ag2, ag2);
        const unsigned long long g3 = pack2(ag3, ag3);

        unsigned long long accA = mul2(g0, r0.x);   // (d[k0], d[k0+1])
        unsigned long long accB = mul2(g0, r0.y);   // (d[k0+2], d[k0+3])
        ffma2(accA, g1, r1.x);  ffma2(accB, g1, r1.y);
        ffma2(accA, g2, r2.x);  ffma2(accB, g2, r2.y);
        ffma2(accA, g3, r3.x);  ffma2(accB, g3, r3.y);

        float4 res;
        unpack2(accA, res.x, res.y);
        unpack2(accB, res.z, res.w);
        *reinterpret_cast<float4*>(obase + inst * 128) = res;
    }
}

// ---------------------------------------------------------------------------
extern "C" void kernel_launch(void* const* d_in, const int* in_sizes, int n_in,
                              void* d_out, int out_size)
{
    const float* inputs      = (const float*)d_in[0];
    const int*   input_types = (const int*)  d_in[1];
    const int*   neigh_list  = (const int*)  d_in[2];
    const float* es1_w = (const float*)d_in[3];
    const float* es1_b = (const float*)d_in[4];
    const float* es2_w = (const float*)d_in[5];
    const float* es2_b = (const float*)d_in[6];
    const float* fs1_w = (const float*)d_in[7];
    const float* fs1_b = (const float*)d_in[8];
    const float* fs2_w = (const float*)d_in[9];
    const float* fs2_b = (const float*)d_in[10];
    const float* en1_w = (const float*)d_in[11];
    const float* en1_b = (const float*)d_in[12];
    const float* en2_w = (const float*)d_in[13];
    const float* en2_b = (const float*)d_in[14];
    const float* en3_w = (const float*)d_in[15];
    const float* en3_b = (const float*)d_in[16];
    float* out = (float*)d_out;

    prep_kernel<<<PACK_BLOCKS + TAB_BLOCKS, 256>>>(
        inputs, input_types,
        es1_w, es1_b, es2_w, es2_b,
        fs1_w, fs1_b, fs2_w, fs2_b,
        en1_w, en1_b, en2_w, en2_b, en3_w, en3_b);

    descriptor_kernel<<<SN / 4, 128>>>(neigh_list, out);
}